// round 2
// baseline (speedup 1.0000x reference)
#include <cuda_runtime.h>
#include <cstdint>

// Problem constants
// B=4, T=2048, D=1024, H=16, HD=64
#define BB 4
#define TT 2048
#define DD 1024
#define HH 16
#define HDIM 64
#define MROWS (BB * TT)          // 8192
#define QKV_COLS (3 * DD)        // 3072

// Scratch (allocation-free: __device__ globals)
__device__ float g_qkv[(size_t)MROWS * QKV_COLS];   // [8192, 3072]
__device__ float g_attn[(size_t)MROWS * DD];        // [8192, 1024]

// ----------------------------------------------------------------------------
// SGEMM: C[M,N] = A[M,K] @ B[N,K]^T (+ bias[N])
// 128x128 block tile, BK=8, 256 threads, 8x8 per-thread micro-tile.
// ----------------------------------------------------------------------------
template <bool HAS_BIAS>
__global__ __launch_bounds__(256) void sgemm_nt(const float* __restrict__ A,
                                                const float* __restrict__ B,
                                                const float* __restrict__ bias,
                                                float* __restrict__ C,
                                                int M, int N, int K)
{
    __shared__ float As[8][132];   // transposed tiles, +4 pad: conflict-free STS
    __shared__ float Bs[8][132];

    const int tid  = threadIdx.x;
    const int tx   = tid & 15;       // 0..15
    const int ty   = tid >> 4;       // 0..15
    const int lrow = tid >> 1;       // 0..127 (load row)
    const int lcol = (tid & 1) << 2; // 0 or 4 (k offset, float4)

    const float* Ap = A + (size_t)(blockIdx.y * 128 + lrow) * K + lcol;
    const float* Bp = B + (size_t)(blockIdx.x * 128 + lrow) * K + lcol;

    float acc[8][8];
#pragma unroll
    for (int i = 0; i < 8; i++)
#pragma unroll
        for (int j = 0; j < 8; j++) acc[i][j] = 0.f;

    for (int k0 = 0; k0 < K; k0 += 8) {
        const float4 a4 = *reinterpret_cast<const float4*>(Ap + k0);
        const float4 b4 = *reinterpret_cast<const float4*>(Bp + k0);
        __syncthreads();   // protect prior iteration's reads
        As[lcol + 0][lrow] = a4.x; As[lcol + 1][lrow] = a4.y;
        As[lcol + 2][lrow] = a4.z; As[lcol + 3][lrow] = a4.w;
        Bs[lcol + 0][lrow] = b4.x; Bs[lcol + 1][lrow] = b4.y;
        Bs[lcol + 2][lrow] = b4.z; Bs[lcol + 3][lrow] = b4.w;
        __syncthreads();

#pragma unroll
        for (int kk = 0; kk < 8; kk++) {
            const float4 a0 = *reinterpret_cast<const float4*>(&As[kk][ty * 8]);
            const float4 a1 = *reinterpret_cast<const float4*>(&As[kk][ty * 8 + 4]);
            const float4 b0 = *reinterpret_cast<const float4*>(&Bs[kk][tx * 8]);
            const float4 b1 = *reinterpret_cast<const float4*>(&Bs[kk][tx * 8 + 4]);
            const float af[8] = {a0.x, a0.y, a0.z, a0.w, a1.x, a1.y, a1.z, a1.w};
            const float bf[8] = {b0.x, b0.y, b0.z, b0.w, b1.x, b1.y, b1.z, b1.w};
#pragma unroll
            for (int i = 0; i < 8; i++)
#pragma unroll
                for (int j = 0; j < 8; j++) acc[i][j] += af[i] * bf[j];
        }
    }

    const int crow = blockIdx.y * 128 + ty * 8;
    const int ccol = blockIdx.x * 128 + tx * 8;
    float bb[8];
#pragma unroll
    for (int j = 0; j < 8; j++) bb[j] = HAS_BIAS ? bias[ccol + j] : 0.f;

#pragma unroll
    for (int i = 0; i < 8; i++) {
        float* cp = C + (size_t)(crow + i) * N + ccol;
        float4 w0, w1;
        w0.x = acc[i][0] + bb[0]; w0.y = acc[i][1] + bb[1];
        w0.z = acc[i][2] + bb[2]; w0.w = acc[i][3] + bb[3];
        w1.x = acc[i][4] + bb[4]; w1.y = acc[i][5] + bb[5];
        w1.z = acc[i][6] + bb[6]; w1.w = acc[i][7] + bb[7];
        *reinterpret_cast<float4*>(cp)     = w0;
        *reinterpret_cast<float4*>(cp + 4) = w1;
    }
}

// ----------------------------------------------------------------------------
// Flash attention (causal), fp32. One block = 64 queries of one (b,h).
// 256 threads as 16x16; each thread owns a 4x4 tile of the 64x64 S matrix.
// smem (dynamic): Qt[64][68], Kt[64][68], Ps[64][68], Vs[64][64]
// ----------------------------------------------------------------------------
#define ATT_SMEM ((3 * 64 * 68 + 64 * 64) * 4)   // 68608 bytes

__global__ __launch_bounds__(256) void flash_attn_kernel(const float* __restrict__ qkv,
                                                         float* __restrict__ attn_out)
{
    extern __shared__ float sm[];
    float (*Qt)[68] = reinterpret_cast<float(*)[68]>(sm);
    float (*Kt)[68] = reinterpret_cast<float(*)[68]>(sm + 64 * 68);
    float (*Ps)[68] = reinterpret_cast<float(*)[68]>(sm + 2 * 64 * 68);
    float (*Vs)[64] = reinterpret_cast<float(*)[64]>(sm + 3 * 64 * 68);

    const int tid = threadIdx.x;
    const int tx  = tid & 15;
    const int ty  = tid >> 4;
    const int qt  = blockIdx.x;          // query tile (0..31)
    const int b   = blockIdx.y >> 4;
    const int h   = blockIdx.y & 15;
    const int q0  = qt * 64;
    const float scale = 0.125f;          // 1/sqrt(64)

    // Load Q tile transposed (pre-scaled): Qt[d][q]
#pragma unroll
    for (int l = 0; l < 4; l++) {
        const int e = tid + l * 256;     // 0..1023
        const int r = e >> 4;            // local q row
        const int c = (e & 15) << 2;     // d (float4)
        const float4 v = *reinterpret_cast<const float4*>(
            qkv + (size_t)(b * TT + q0 + r) * QKV_COLS + h * HDIM + c);
        Qt[c + 0][r] = v.x * scale; Qt[c + 1][r] = v.y * scale;
        Qt[c + 2][r] = v.z * scale; Qt[c + 3][r] = v.w * scale;
    }

    float m_i[4], l_i[4], o[4][4];
#pragma unroll
    for (int i = 0; i < 4; i++) {
        m_i[i] = -3.0e38f; l_i[i] = 0.f;
#pragma unroll
        for (int j = 0; j < 4; j++) o[i][j] = 0.f;
    }

    for (int kt = 0; kt <= qt; kt++) {
        const int k0 = kt * 64;
        __syncthreads();   // protect Qt (first iter) / Ps,Vs (later iters)
#pragma unroll
        for (int l = 0; l < 4; l++) {
            const int e = tid + l * 256;
            const int r = e >> 4;
            const int c = (e & 15) << 2;
            const size_t base = (size_t)(b * TT + k0 + r) * QKV_COLS + h * HDIM + c;
            const float4 kv = *reinterpret_cast<const float4*>(qkv + base + DD);
            const float4 vv = *reinterpret_cast<const float4*>(qkv + base + 2 * DD);
            Kt[c + 0][r] = kv.x; Kt[c + 1][r] = kv.y;
            Kt[c + 2][r] = kv.z; Kt[c + 3][r] = kv.w;
            *reinterpret_cast<float4*>(&Vs[r][c]) = vv;
        }
        __syncthreads();

        // S = (Q*scale) K^T  — 4x4 per thread
        float s[4][4];
#pragma unroll
        for (int i = 0; i < 4; i++)
#pragma unroll
            for (int j = 0; j < 4; j++) s[i][j] = 0.f;

#pragma unroll 16
        for (int d = 0; d < 64; d++) {
            const float4 qf = *reinterpret_cast<const float4*>(&Qt[d][ty << 2]);
            const float4 kf = *reinterpret_cast<const float4*>(&Kt[d][tx << 2]);
            const float qa[4] = {qf.x, qf.y, qf.z, qf.w};
            const float ka[4] = {kf.x, kf.y, kf.z, kf.w};
#pragma unroll
            for (int i = 0; i < 4; i++)
#pragma unroll
                for (int j = 0; j < 4; j++) s[i][j] += qa[i] * ka[j];
        }

        if (kt == qt) {   // causal mask on the diagonal tile
#pragma unroll
            for (int i = 0; i < 4; i++)
#pragma unroll
                for (int j = 0; j < 4; j++)
                    if (((tx << 2) + j) > ((ty << 2) + i)) s[i][j] = -3.0e38f;
        }

        // online softmax: row groups are 16 contiguous lanes (xor 8,4,2,1)
#pragma unroll
        for (int i = 0; i < 4; i++) {
            float tm = fmaxf(fmaxf(s[i][0], s[i][1]), fmaxf(s[i][2], s[i][3]));
#pragma unroll
            for (int off = 8; off >= 1; off >>= 1)
                tm = fmaxf(tm, __shfl_xor_sync(0xffffffffu, tm, off));
            const float mn   = fmaxf(m_i[i], tm);
            const float corr = __expf(m_i[i] - mn);
            float rs = 0.f;
#pragma unroll
            for (int j = 0; j < 4; j++) { s[i][j] = __expf(s[i][j] - mn); rs += s[i][j]; }
#pragma unroll
            for (int off = 8; off >= 1; off >>= 1)
                rs += __shfl_xor_sync(0xffffffffu, rs, off);
            l_i[i] = l_i[i] * corr + rs;
            m_i[i] = mn;
#pragma unroll
            for (int j = 0; j < 4; j++) o[i][j] *= corr;
        }

        // stage P, then O += P @ V
#pragma unroll
        for (int i = 0; i < 4; i++)
#pragma unroll
            for (int j = 0; j < 4; j++) Ps[(ty << 2) + i][(tx << 2) + j] = s[i][j];
        __syncthreads();

#pragma unroll 16
        for (int k = 0; k < 64; k++) {
            const float4 vf = *reinterpret_cast<const float4*>(&Vs[k][tx << 2]);
#pragma unroll
            for (int i = 0; i < 4; i++) {
                const float p = Ps[(ty << 2) + i][k];
                o[i][0] += p * vf.x; o[i][1] += p * vf.y;
                o[i][2] += p * vf.z; o[i][3] += p * vf.w;
            }
        }
    }

    // epilogue: normalize, write [B,T,D] with heads concatenated
#pragma unroll
    for (int i = 0; i < 4; i++) {
        const float inv = 1.0f / l_i[i];
        float4 r;
        r.x = o[i][0] * inv; r.y = o[i][1] * inv;
        r.z = o[i][2] * inv; r.w = o[i][3] * inv;
        const int q = q0 + (ty << 2) + i;
        *reinterpret_cast<float4*>(
            attn_out + (size_t)(b * TT + q) * DD + h * HDIM + (tx << 2)) = r;
    }
}

// ----------------------------------------------------------------------------
extern "C" void kernel_launch(void* const* d_in, const int* in_sizes, int n_in,
                              void* d_out, int out_size)
{
    const float* x     = (const float*)d_in[0];   // [4,2048,1024]
    const float* Wqkv  = (const float*)d_in[1];   // [3072,1024]
    const float* Wproj = (const float*)d_in[2];   // [1024,1024]
    const float* bproj = (const float*)d_in[3];   // [1024]
    float* out = (float*)d_out;                   // [4,2048,1024]

    float *qkv, *attn;
    cudaGetSymbolAddress((void**)&qkv,  g_qkv);
    cudaGetSymbolAddress((void**)&attn, g_attn);

    // 1) QKV projection: [8192,3072] = x @ W_qkv^T
    {
        dim3 grid(QKV_COLS / 128, MROWS / 128);
        sgemm_nt<false><<<grid, 256>>>(x, Wqkv, nullptr, qkv, MROWS, QKV_COLS, DD);
    }

    // 2) causal flash attention -> [8192,1024] (heads concatenated)
    {
        cudaFuncSetAttribute(flash_attn_kernel,
                             cudaFuncAttributeMaxDynamicSharedMemorySize, ATT_SMEM);
        dim3 grid(TT / 64, BB * HH);
        flash_attn_kernel<<<grid, 256, ATT_SMEM>>>(qkv, attn);
    }

    // 3) output projection: out = attn @ W_proj^T + b_proj
    {
        dim3 grid(DD / 128, MROWS / 128);
        sgemm_nt<true><<<grid, 256>>>(attn, Wproj, bproj, out, MROWS, DD, DD);
    }
}

// round 3
// speedup vs baseline: 1.9898x; 1.9898x over previous
#include <cuda_runtime.h>
#include <cuda_bf16.h>
#include <cstdint>

// B=4, T=2048, D=1024, H=16, HD=64
#define BB 4
#define TT 2048
#define DD 1024
#define HH 16
#define HDIM 64
#define MROWS (BB * TT)          // 8192
#define QKV_COLS (3 * DD)        // 3072

// ---------------- scratch (__device__ globals; allocation-free) -------------
__device__ __nv_bfloat16 g_xh[(size_t)MROWS * DD];
__device__ __nv_bfloat16 g_xl[(size_t)MROWS * DD];
__device__ __nv_bfloat16 g_wqh[(size_t)QKV_COLS * DD];
__device__ __nv_bfloat16 g_wql[(size_t)QKV_COLS * DD];
__device__ __nv_bfloat16 g_wph[(size_t)DD * DD];
__device__ __nv_bfloat16 g_wpl[(size_t)DD * DD];
__device__ __nv_bfloat16 g_qkvh[(size_t)MROWS * QKV_COLS];
__device__ __nv_bfloat16 g_qkvl[(size_t)MROWS * QKV_COLS];
__device__ __nv_bfloat16 g_ah[(size_t)MROWS * DD];
__device__ __nv_bfloat16 g_al[(size_t)MROWS * DD];

// ---------------- helpers ---------------------------------------------------
__device__ __forceinline__ void mma_bf16(float* c, const uint32_t* a, const uint32_t* b) {
    asm volatile(
        "mma.sync.aligned.m16n8k16.row.col.f32.bf16.bf16.f32 "
        "{%0,%1,%2,%3},{%4,%5,%6,%7},{%8,%9},{%0,%1,%2,%3};"
        : "+f"(c[0]), "+f"(c[1]), "+f"(c[2]), "+f"(c[3])
        : "r"(a[0]), "r"(a[1]), "r"(a[2]), "r"(a[3]), "r"(b[0]), "r"(b[1]));
}

__device__ __forceinline__ void cp16(void* smem_dst, const void* gsrc) {
    uint32_t s = (uint32_t)__cvta_generic_to_shared(smem_dst);
    asm volatile("cp.async.ca.shared.global [%0], [%1], 16;" :: "r"(s), "l"(gsrc));
}
__device__ __forceinline__ void cp_commit() { asm volatile("cp.async.commit_group;"); }
template <int N> __device__ __forceinline__ void cp_wait() {
    asm volatile("cp.async.wait_group %0;" :: "n"(N));
}

__device__ __forceinline__ uint32_t lds32(const __nv_bfloat16* p) {
    return *reinterpret_cast<const uint32_t*>(p);
}

// ---------------- split fp32 -> (hi, lo) bf16 -------------------------------
__global__ void split_kernel(const float* __restrict__ x,
                             __nv_bfloat16* __restrict__ h,
                             __nv_bfloat16* __restrict__ l, int n4)
{
    int i = blockIdx.x * blockDim.x + threadIdx.x;
    if (i >= n4) return;
    float4 v = reinterpret_cast<const float4*>(x)[i];
    float vv[4] = {v.x, v.y, v.z, v.w};
    __nv_bfloat16 hh[4], ll[4];
#pragma unroll
    for (int k = 0; k < 4; k++) {
        hh[k] = __float2bfloat16(vv[k]);
        ll[k] = __float2bfloat16(vv[k] - __bfloat162float(hh[k]));
    }
    reinterpret_cast<uint2*>(h)[i] = *reinterpret_cast<uint2*>(hh);
    reinterpret_cast<uint2*>(l)[i] = *reinterpret_cast<uint2*>(ll);
}

// ---------------- split-bf16 GEMM: C[M,N] = A @ B^T (+bias) -----------------
// 128x128 tile, BK=32, 256 thr, 8 warps (4m x 2n), warp 32x64. cp.async x2.
#define GST 40                      // smem row stride (bf16)
#define GTILE (128 * GST)           // 5120 bf16
#define G_AH 0
#define G_AL GTILE
#define G_BH (2 * GTILE)
#define G_BL (3 * GTILE)
#define G_STAGE (4 * GTILE)         // 20480 bf16
#define GEMM_SMEM (2 * G_STAGE * 2) // 81920 bytes

template <bool SPLIT_OUT, bool HAS_BIAS>
__global__ __launch_bounds__(256) void gemm_sp(
    const __nv_bfloat16* __restrict__ Ahg, const __nv_bfloat16* __restrict__ Alg,
    const __nv_bfloat16* __restrict__ Bhg, const __nv_bfloat16* __restrict__ Blg,
    const float* __restrict__ bias,
    float* __restrict__ Cf,
    __nv_bfloat16* __restrict__ Chg, __nv_bfloat16* __restrict__ Clg,
    int M, int N, int K)
{
    extern __shared__ __nv_bfloat16 sm[];
    const int tid  = threadIdx.x;
    const int lane = tid & 31;
    const int wid  = tid >> 5;
    const int g    = lane >> 2;
    const int q    = lane & 3;
    const int m0   = (wid & 3) * 32;
    const int n0   = (wid >> 2) * 64;
    const int bRow = blockIdx.y * 128;
    const int bCol = blockIdx.x * 128;

    const int lrow = tid >> 2;          // 0..63
    const int lc8  = (tid & 3) * 8;     // 0,8,16,24

    float c[2][8][4];
#pragma unroll
    for (int m = 0; m < 2; m++)
#pragma unroll
        for (int n = 0; n < 8; n++)
#pragma unroll
            for (int r = 0; r < 4; r++) c[m][n][r] = 0.f;

    const int NT = K / 32;

    auto issue = [&](int t, int stg) {
        const int k0 = t * 32;
        __nv_bfloat16* s = sm + stg * G_STAGE;
        const size_t aoff0 = (size_t)(bRow + lrow) * K + k0 + lc8;
        const size_t aoff1 = (size_t)(bRow + lrow + 64) * K + k0 + lc8;
        const size_t boff0 = (size_t)(bCol + lrow) * K + k0 + lc8;
        const size_t boff1 = (size_t)(bCol + lrow + 64) * K + k0 + lc8;
        cp16(s + G_AH + lrow * GST + lc8,        Ahg + aoff0);
        cp16(s + G_AH + (lrow + 64) * GST + lc8, Ahg + aoff1);
        cp16(s + G_AL + lrow * GST + lc8,        Alg + aoff0);
        cp16(s + G_AL + (lrow + 64) * GST + lc8, Alg + aoff1);
        cp16(s + G_BH + lrow * GST + lc8,        Bhg + boff0);
        cp16(s + G_BH + (lrow + 64) * GST + lc8, Bhg + boff1);
        cp16(s + G_BL + lrow * GST + lc8,        Blg + boff0);
        cp16(s + G_BL + (lrow + 64) * GST + lc8, Blg + boff1);
    };

    issue(0, 0);
    cp_commit();

    for (int t = 0; t < NT; ++t) {
        if (t + 1 < NT) { issue(t + 1, (t + 1) & 1); cp_commit(); cp_wait<1>(); }
        else            { cp_wait<0>(); }
        __syncthreads();

        const __nv_bfloat16* s = sm + (t & 1) * G_STAGE;
#pragma unroll
        for (int kk = 0; kk < 2; kk++) {
            uint32_t ah[2][4], al[2][4];
#pragma unroll
            for (int m = 0; m < 2; m++) {
                const int base = (m0 + m * 16 + g) * GST + kk * 16 + 2 * q;
                ah[m][0] = lds32(s + G_AH + base);
                ah[m][1] = lds32(s + G_AH + base + 8 * GST);
                ah[m][2] = lds32(s + G_AH + base + 8);
                ah[m][3] = lds32(s + G_AH + base + 8 * GST + 8);
                al[m][0] = lds32(s + G_AL + base);
                al[m][1] = lds32(s + G_AL + base + 8 * GST);
                al[m][2] = lds32(s + G_AL + base + 8);
                al[m][3] = lds32(s + G_AL + base + 8 * GST + 8);
            }
#pragma unroll
            for (int n = 0; n < 8; n++) {
                const int bb = (n0 + n * 8 + g) * GST + kk * 16 + 2 * q;
                uint32_t bh[2], bl[2];
                bh[0] = lds32(s + G_BH + bb);
                bh[1] = lds32(s + G_BH + bb + 8);
                bl[0] = lds32(s + G_BL + bb);
                bl[1] = lds32(s + G_BL + bb + 8);
#pragma unroll
                for (int m = 0; m < 2; m++) {
                    mma_bf16(c[m][n], ah[m], bh);
                    mma_bf16(c[m][n], al[m], bh);
                    mma_bf16(c[m][n], ah[m], bl);
                }
            }
        }
        __syncthreads();
    }

    // epilogue
#pragma unroll
    for (int m = 0; m < 2; m++) {
#pragma unroll
        for (int n = 0; n < 8; n++) {
            const int row = bRow + m0 + m * 16 + g;
            const int col = bCol + n0 + n * 8 + 2 * q;
#pragma unroll
            for (int half = 0; half < 2; half++) {
                const int r = row + half * 8;
                float v0 = c[m][n][half * 2 + 0];
                float v1 = c[m][n][half * 2 + 1];
                if (HAS_BIAS) { v0 += bias[col]; v1 += bias[col + 1]; }
                if (SPLIT_OUT) {
                    __nv_bfloat16 h0 = __float2bfloat16(v0);
                    __nv_bfloat16 h1 = __float2bfloat16(v1);
                    __nv_bfloat16 l0 = __float2bfloat16(v0 - __bfloat162float(h0));
                    __nv_bfloat16 l1 = __float2bfloat16(v1 - __bfloat162float(h1));
                    __nv_bfloat162 hp; hp.x = h0; hp.y = h1;
                    __nv_bfloat162 lp; lp.x = l0; lp.y = l1;
                    *reinterpret_cast<__nv_bfloat162*>(&Chg[(size_t)r * N + col]) = hp;
                    *reinterpret_cast<__nv_bfloat162*>(&Clg[(size_t)r * N + col]) = lp;
                } else {
                    float2 w; w.x = v0; w.y = v1;
                    *reinterpret_cast<float2*>(&Cf[(size_t)r * N + col]) = w;
                }
            }
        }
    }
}

// ---------------- split-bf16 causal flash attention --------------------------
// block = 128 thr (4 warps), 64-query tile of one (b,h). warp w: rows 16w..16w+15.
#define FST 72                       // smem row stride (bf16)
#define FTILE (64 * FST)             // 4608
#define F_QH 0
#define F_QL (1 * FTILE)
#define F_KH (2 * FTILE)
#define F_KL (3 * FTILE)
#define F_VH (4 * FTILE)
#define F_VL (5 * FTILE)
#define F_PH (6 * FTILE)
#define F_PL (7 * FTILE)
#define FLASH_SMEM (8 * FTILE * 2)   // 73728 bytes

__global__ __launch_bounds__(128) void flash_sp(
    const __nv_bfloat16* __restrict__ qkvh,
    const __nv_bfloat16* __restrict__ qkvl,
    __nv_bfloat16* __restrict__ Oh, __nv_bfloat16* __restrict__ Ol)
{
    extern __shared__ __nv_bfloat16 sm[];
    __nv_bfloat16* Qh = sm + F_QH;  __nv_bfloat16* Ql = sm + F_QL;
    __nv_bfloat16* Kh = sm + F_KH;  __nv_bfloat16* Kl = sm + F_KL;
    __nv_bfloat16* Vh = sm + F_VH;  __nv_bfloat16* Vl = sm + F_VL;
    __nv_bfloat16* Ph = sm + F_PH;  __nv_bfloat16* Pl = sm + F_PL;

    const int tid  = threadIdx.x;
    const int lane = tid & 31;
    const int wid  = tid >> 5;
    const int g    = lane >> 2;
    const int q    = lane & 3;
    const int qt   = blockIdx.x;
    const int b    = blockIdx.y >> 4;
    const int h    = blockIdx.y & 15;
    const int q0   = qt * 64;
    const int rl0  = wid * 16 + g;
    const int rl1  = rl0 + 8;

    // load Q (scaled by 1/8, exact power of two)
    __nv_bfloat162 sc2; sc2.x = __float2bfloat16(0.125f); sc2.y = sc2.x;
#pragma unroll
    for (int l = 0; l < 4; l++) {
        const int idx = tid + l * 128;
        const int r = idx >> 3;
        const int c8 = (idx & 7) * 8;
        const size_t off = (size_t)(b * TT + q0 + r) * QKV_COLS + h * HDIM + c8;
        uint4 vh4 = *reinterpret_cast<const uint4*>(qkvh + off);
        uint4 vl4 = *reinterpret_cast<const uint4*>(qkvl + off);
        __nv_bfloat162* ph = reinterpret_cast<__nv_bfloat162*>(&vh4);
        __nv_bfloat162* pl = reinterpret_cast<__nv_bfloat162*>(&vl4);
#pragma unroll
        for (int i = 0; i < 4; i++) { ph[i] = __hmul2(ph[i], sc2); pl[i] = __hmul2(pl[i], sc2); }
        *reinterpret_cast<uint4*>(&Qh[r * FST + c8]) = vh4;
        *reinterpret_cast<uint4*>(&Ql[r * FST + c8]) = vl4;
    }

    float m0r = -1e30f, m1r = -1e30f, l0r = 0.f, l1r = 0.f;
    float o[8][4];
#pragma unroll
    for (int j = 0; j < 8; j++)
#pragma unroll
        for (int r = 0; r < 4; r++) o[j][r] = 0.f;

    for (int kt = 0; kt <= qt; kt++) {
        __syncthreads();
        // load K and transposed V
#pragma unroll
        for (int l = 0; l < 4; l++) {
            const int idx = tid + l * 128;
            const int r = idx >> 3;
            const int c8 = (idx & 7) * 8;
            const size_t base = (size_t)(b * TT + kt * 64 + r) * QKV_COLS + h * HDIM + c8;
            uint4 kh4 = *reinterpret_cast<const uint4*>(qkvh + base + DD);
            uint4 kl4 = *reinterpret_cast<const uint4*>(qkvl + base + DD);
            *reinterpret_cast<uint4*>(&Kh[r * FST + c8]) = kh4;
            *reinterpret_cast<uint4*>(&Kl[r * FST + c8]) = kl4;
            uint4 vh4 = *reinterpret_cast<const uint4*>(qkvh + base + 2 * DD);
            uint4 vl4 = *reinterpret_cast<const uint4*>(qkvl + base + 2 * DD);
            __nv_bfloat16 eh[8], el[8];
            *reinterpret_cast<uint4*>(eh) = vh4;
            *reinterpret_cast<uint4*>(el) = vl4;
#pragma unroll
            for (int i = 0; i < 8; i++) {
                Vh[(c8 + i) * FST + r] = eh[i];
                Vl[(c8 + i) * FST + r] = el[i];
            }
        }
        __syncthreads();

        // S = Q K^T (split: hh + lh + hl)
        float s[8][4];
#pragma unroll
        for (int j = 0; j < 8; j++)
#pragma unroll
            for (int r = 0; r < 4; r++) s[j][r] = 0.f;

#pragma unroll
        for (int kk = 0; kk < 4; kk++) {
            uint32_t qh[4], ql[4];
            const int base = rl0 * FST + kk * 16 + 2 * q;
            qh[0] = lds32(Qh + base);            qh[1] = lds32(Qh + base + 8 * FST);
            qh[2] = lds32(Qh + base + 8);        qh[3] = lds32(Qh + base + 8 * FST + 8);
            ql[0] = lds32(Ql + base);            ql[1] = lds32(Ql + base + 8 * FST);
            ql[2] = lds32(Ql + base + 8);        ql[3] = lds32(Ql + base + 8 * FST + 8);
#pragma unroll
            for (int j = 0; j < 8; j++) {
                const int bb = (j * 8 + g) * FST + kk * 16 + 2 * q;
                uint32_t kh2[2], kl2[2];
                kh2[0] = lds32(Kh + bb); kh2[1] = lds32(Kh + bb + 8);
                kl2[0] = lds32(Kl + bb); kl2[1] = lds32(Kl + bb + 8);
                mma_bf16(s[j], qh, kh2);
                mma_bf16(s[j], ql, kh2);
                mma_bf16(s[j], qh, kl2);
            }
        }

        if (kt == qt) {   // causal mask, diagonal tile
#pragma unroll
            for (int j = 0; j < 8; j++) {
                const int cj = j * 8 + 2 * q;
                if (cj     > rl0) s[j][0] = -1e30f;
                if (cj + 1 > rl0) s[j][1] = -1e30f;
                if (cj     > rl1) s[j][2] = -1e30f;
                if (cj + 1 > rl1) s[j][3] = -1e30f;
            }
        }

        // online softmax, row r0 (regs 0,1) and r1 (regs 2,3)
        {
            float tm = -1e30f;
#pragma unroll
            for (int j = 0; j < 8; j++) tm = fmaxf(tm, fmaxf(s[j][0], s[j][1]));
            tm = fmaxf(tm, __shfl_xor_sync(0xffffffffu, tm, 1));
            tm = fmaxf(tm, __shfl_xor_sync(0xffffffffu, tm, 2));
            const float mn = fmaxf(m0r, tm);
            const float corr = __expf(m0r - mn);
            m0r = mn;
            float rs = 0.f;
#pragma unroll
            for (int j = 0; j < 8; j++) {
                s[j][0] = __expf(s[j][0] - mn); rs += s[j][0];
                s[j][1] = __expf(s[j][1] - mn); rs += s[j][1];
            }
            rs += __shfl_xor_sync(0xffffffffu, rs, 1);
            rs += __shfl_xor_sync(0xffffffffu, rs, 2);
            l0r = l0r * corr + rs;
#pragma unroll
            for (int j = 0; j < 8; j++) { o[j][0] *= corr; o[j][1] *= corr; }
        }
        {
            float tm = -1e30f;
#pragma unroll
            for (int j = 0; j < 8; j++) tm = fmaxf(tm, fmaxf(s[j][2], s[j][3]));
            tm = fmaxf(tm, __shfl_xor_sync(0xffffffffu, tm, 1));
            tm = fmaxf(tm, __shfl_xor_sync(0xffffffffu, tm, 2));
            const float mn = fmaxf(m1r, tm);
            const float corr = __expf(m1r - mn);
            m1r = mn;
            float rs = 0.f;
#pragma unroll
            for (int j = 0; j < 8; j++) {
                s[j][2] = __expf(s[j][2] - mn); rs += s[j][2];
                s[j][3] = __expf(s[j][3] - mn); rs += s[j][3];
            }
            rs += __shfl_xor_sync(0xffffffffu, rs, 1);
            rs += __shfl_xor_sync(0xffffffffu, rs, 2);
            l1r = l1r * corr + rs;
#pragma unroll
            for (int j = 0; j < 8; j++) { o[j][2] *= corr; o[j][3] *= corr; }
        }

        // stage split P
#pragma unroll
        for (int j = 0; j < 8; j++) {
            const int col = j * 8 + 2 * q;
#pragma unroll
            for (int half = 0; half < 2; half++) {
                const int r = (half == 0) ? rl0 : rl1;
                const float v0 = s[j][half * 2 + 0];
                const float v1 = s[j][half * 2 + 1];
                __nv_bfloat16 h0 = __float2bfloat16(v0);
                __nv_bfloat16 h1 = __float2bfloat16(v1);
                __nv_bfloat16 l0v = __float2bfloat16(v0 - __bfloat162float(h0));
                __nv_bfloat16 l1v = __float2bfloat16(v1 - __bfloat162float(h1));
                __nv_bfloat162 hp; hp.x = h0; hp.y = h1;
                __nv_bfloat162 lp; lp.x = l0v; lp.y = l1v;
                *reinterpret_cast<__nv_bfloat162*>(&Ph[r * FST + col]) = hp;
                *reinterpret_cast<__nv_bfloat162*>(&Pl[r * FST + col]) = lp;
            }
        }
        __syncthreads();

        // O += P V (split)
#pragma unroll
        for (int kk = 0; kk < 4; kk++) {
            uint32_t ph[4], pl[4];
            const int base = rl0 * FST + kk * 16 + 2 * q;
            ph[0] = lds32(Ph + base);            ph[1] = lds32(Ph + base + 8 * FST);
            ph[2] = lds32(Ph + base + 8);        ph[3] = lds32(Ph + base + 8 * FST + 8);
            pl[0] = lds32(Pl + base);            pl[1] = lds32(Pl + base + 8 * FST);
            pl[2] = lds32(Pl + base + 8);        pl[3] = lds32(Pl + base + 8 * FST + 8);
#pragma unroll
            for (int j = 0; j < 8; j++) {
                const int bb = (j * 8 + g) * FST + kk * 16 + 2 * q;
                uint32_t vh2[2], vl2[2];
                vh2[0] = lds32(Vh + bb); vh2[1] = lds32(Vh + bb + 8);
                vl2[0] = lds32(Vl + bb); vl2[1] = lds32(Vl + bb + 8);
                mma_bf16(o[j], ph, vh2);
                mma_bf16(o[j], pl, vh2);
                mma_bf16(o[j], ph, vl2);
            }
        }
    }

    // epilogue: normalize, split, store
    const float inv0 = 1.0f / l0r;
    const float inv1 = 1.0f / l1r;
#pragma unroll
    for (int j = 0; j < 8; j++) {
        const int col = h * HDIM + j * 8 + 2 * q;
#pragma unroll
        for (int half = 0; half < 2; half++) {
            const int r = (half == 0) ? rl0 : rl1;
            const float inv = (half == 0) ? inv0 : inv1;
            const float v0 = o[j][half * 2 + 0] * inv;
            const float v1 = o[j][half * 2 + 1] * inv;
            __nv_bfloat16 h0 = __float2bfloat16(v0);
            __nv_bfloat16 h1 = __float2bfloat16(v1);
            __nv_bfloat16 l0v = __float2bfloat16(v0 - __bfloat162float(h0));
            __nv_bfloat16 l1v = __float2bfloat16(v1 - __bfloat162float(h1));
            __nv_bfloat162 hp; hp.x = h0; hp.y = h1;
            __nv_bfloat162 lp; lp.x = l0v; lp.y = l1v;
            const size_t off = (size_t)(b * TT + q0 + r) * DD + col;
            *reinterpret_cast<__nv_bfloat162*>(&Oh[off]) = hp;
            *reinterpret_cast<__nv_bfloat162*>(&Ol[off]) = lp;
        }
    }
}

// ---------------------------------------------------------------------------
extern "C" void kernel_launch(void* const* d_in, const int* in_sizes, int n_in,
                              void* d_out, int out_size)
{
    const float* x     = (const float*)d_in[0];
    const float* Wqkv  = (const float*)d_in[1];
    const float* Wproj = (const float*)d_in[2];
    const float* bproj = (const float*)d_in[3];
    float* out = (float*)d_out;

    __nv_bfloat16 *xh, *xl, *wqh, *wql, *wph, *wpl, *qkvh, *qkvl, *ah, *al;
    cudaGetSymbolAddress((void**)&xh,   g_xh);
    cudaGetSymbolAddress((void**)&xl,   g_xl);
    cudaGetSymbolAddress((void**)&wqh,  g_wqh);
    cudaGetSymbolAddress((void**)&wql,  g_wql);
    cudaGetSymbolAddress((void**)&wph,  g_wph);
    cudaGetSymbolAddress((void**)&wpl,  g_wpl);
    cudaGetSymbolAddress((void**)&qkvh, g_qkvh);
    cudaGetSymbolAddress((void**)&qkvl, g_qkvl);
    cudaGetSymbolAddress((void**)&ah,   g_ah);
    cudaGetSymbolAddress((void**)&al,   g_al);

    cudaFuncSetAttribute(gemm_sp<true, false>,
                         cudaFuncAttributeMaxDynamicSharedMemorySize, GEMM_SMEM);
    cudaFuncSetAttribute(gemm_sp<false, true>,
                         cudaFuncAttributeMaxDynamicSharedMemorySize, GEMM_SMEM);
    cudaFuncSetAttribute(flash_sp,
                         cudaFuncAttributeMaxDynamicSharedMemorySize, FLASH_SMEM);

    // splits
    split_kernel<<<(MROWS * DD / 4 + 255) / 256, 256>>>(x, xh, xl, MROWS * DD / 4);
    split_kernel<<<(QKV_COLS * DD / 4 + 255) / 256, 256>>>(Wqkv, wqh, wql, QKV_COLS * DD / 4);
    split_kernel<<<(DD * DD / 4 + 255) / 256, 256>>>(Wproj, wph, wpl, DD * DD / 4);

    // 1) QKV projection (split output for attention)
    {
        dim3 grid(QKV_COLS / 128, MROWS / 128);
        gemm_sp<true, false><<<grid, 256, GEMM_SMEM>>>(
            xh, xl, wqh, wql, nullptr, nullptr, qkvh, qkvl, MROWS, QKV_COLS, DD);
    }
    // 2) causal flash attention (split output)
    {
        dim3 grid(TT / 64, BB * HH);
        flash_sp<<<grid, 128, FLASH_SMEM>>>(qkvh, qkvl, ah, al);
    }
    // 3) output projection (fp32 out, bias)
    {
        dim3 grid(DD / 128, MROWS / 128);
        gemm_sp<false, true><<<grid, 256, GEMM_SMEM>>>(
            ah, al, wph, wpl, bproj, out, nullptr, nullptr, MROWS, DD, DD);
    }
}

// round 5
// speedup vs baseline: 2.2536x; 1.1326x over previous
#include <cuda_runtime.h>
#include <cuda_bf16.h>
#include <cstdint>

// B=4, T=2048, D=1024, H=16, HD=64
#define BB 4
#define TT 2048
#define DD 1024
#define HH 16
#define HDIM 64
#define MROWS (BB * TT)          // 8192
#define QKV_COLS (3 * DD)        // 3072

// ---------------- scratch (__device__ globals; allocation-free) -------------
__device__ __nv_bfloat16 g_xh[(size_t)MROWS * DD];
__device__ __nv_bfloat16 g_xl[(size_t)MROWS * DD];
__device__ __nv_bfloat16 g_wqh[(size_t)QKV_COLS * DD];
__device__ __nv_bfloat16 g_wql[(size_t)QKV_COLS * DD];
__device__ __nv_bfloat16 g_wph[(size_t)DD * DD];
__device__ __nv_bfloat16 g_wpl[(size_t)DD * DD];
__device__ __nv_bfloat16 g_qkvh[(size_t)MROWS * QKV_COLS];
__device__ __nv_bfloat16 g_qkvl[(size_t)MROWS * QKV_COLS];
__device__ __nv_bfloat16 g_ah[(size_t)MROWS * DD];
__device__ __nv_bfloat16 g_al[(size_t)MROWS * DD];

// ---------------- helpers ---------------------------------------------------
__device__ __forceinline__ void mma_bf16(float* c, const uint32_t* a, const uint32_t* b) {
    asm volatile(
        "mma.sync.aligned.m16n8k16.row.col.f32.bf16.bf16.f32 "
        "{%0,%1,%2,%3},{%4,%5,%6,%7},{%8,%9},{%0,%1,%2,%3};"
        : "+f"(c[0]), "+f"(c[1]), "+f"(c[2]), "+f"(c[3])
        : "r"(a[0]), "r"(a[1]), "r"(a[2]), "r"(a[3]), "r"(b[0]), "r"(b[1]));
}

__device__ __forceinline__ void cp16(void* smem_dst, const void* gsrc) {
    uint32_t s = (uint32_t)__cvta_generic_to_shared(smem_dst);
    asm volatile("cp.async.ca.shared.global [%0], [%1], 16;" :: "r"(s), "l"(gsrc));
}
__device__ __forceinline__ void cp_commit() { asm volatile("cp.async.commit_group;"); }
template <int N> __device__ __forceinline__ void cp_wait() {
    asm volatile("cp.async.wait_group %0;" :: "n"(N));
}
__device__ __forceinline__ uint32_t lds32(const __nv_bfloat16* p) {
    return *reinterpret_cast<const uint32_t*>(p);
}

// ---------------- split fp32 -> (hi, lo) bf16 -------------------------------
__global__ void split_kernel(const float* __restrict__ x,
                             __nv_bfloat16* __restrict__ h,
                             __nv_bfloat16* __restrict__ l, int n4)
{
    int i = blockIdx.x * blockDim.x + threadIdx.x;
    if (i >= n4) return;
    float4 v = reinterpret_cast<const float4*>(x)[i];
    float vv[4] = {v.x, v.y, v.z, v.w};
    __nv_bfloat16 hh[4], ll[4];
#pragma unroll
    for (int k = 0; k < 4; k++) {
        hh[k] = __float2bfloat16(vv[k]);
        ll[k] = __float2bfloat16(vv[k] - __bfloat162float(hh[k]));
    }
    reinterpret_cast<uint2*>(h)[i] = *reinterpret_cast<uint2*>(hh);
    reinterpret_cast<uint2*>(l)[i] = *reinterpret_cast<uint2*>(ll);
}

// ---------------- split-bf16 GEMM: C[M,N] = A @ B^T (+bias) -----------------
// 128x128 tile, BK=32, 256 thr, 8 warps (4m x 2n), warp 32x64. cp.async x2.
// __launch_bounds__(256, 2): cap regs at 128 so 2 CTAs/SM co-reside.
#define GST 40                      // smem row stride (bf16)
#define GTILE (128 * GST)           // 5120 bf16
#define G_AH 0
#define G_AL GTILE
#define G_BH (2 * GTILE)
#define G_BL (3 * GTILE)
#define G_STAGE (4 * GTILE)         // 20480 bf16
#define GEMM_SMEM (2 * G_STAGE * 2) // 81920 bytes

template <bool SPLIT_OUT, bool HAS_BIAS>
__global__ __launch_bounds__(256, 2) void gemm_sp(
    const __nv_bfloat16* __restrict__ Ahg, const __nv_bfloat16* __restrict__ Alg,
    const __nv_bfloat16* __restrict__ Bhg, const __nv_bfloat16* __restrict__ Blg,
    const float* __restrict__ bias,
    float* __restrict__ Cf,
    __nv_bfloat16* __restrict__ Chg, __nv_bfloat16* __restrict__ Clg,
    int M, int N, int K)
{
    extern __shared__ __nv_bfloat16 sm[];
    const int tid  = threadIdx.x;
    const int lane = tid & 31;
    const int wid  = tid >> 5;
    const int g    = lane >> 2;
    const int q    = lane & 3;
    const int m0   = (wid & 3) * 32;
    const int n0   = (wid >> 2) * 64;
    const int bRow = blockIdx.y * 128;
    const int bCol = blockIdx.x * 128;

    const int lrow = tid >> 2;          // 0..63
    const int lc8  = (tid & 3) * 8;     // 0,8,16,24

    float c[2][8][4];
#pragma unroll
    for (int m = 0; m < 2; m++)
#pragma unroll
        for (int n = 0; n < 8; n++)
#pragma unroll
            for (int r = 0; r < 4; r++) c[m][n][r] = 0.f;

    const int NT = K / 32;

    auto issue = [&](int t, int stg) {
        const int k0 = t * 32;
        __nv_bfloat16* s = sm + stg * G_STAGE;
        const size_t aoff0 = (size_t)(bRow + lrow) * K + k0 + lc8;
        const size_t aoff1 = (size_t)(bRow + lrow + 64) * K + k0 + lc8;
        const size_t boff0 = (size_t)(bCol + lrow) * K + k0 + lc8;
        const size_t boff1 = (size_t)(bCol + lrow + 64) * K + k0 + lc8;
        cp16(s + G_AH + lrow * GST + lc8,        Ahg + aoff0);
        cp16(s + G_AH + (lrow + 64) * GST + lc8, Ahg + aoff1);
        cp16(s + G_AL + lrow * GST + lc8,        Alg + aoff0);
        cp16(s + G_AL + (lrow + 64) * GST + lc8, Alg + aoff1);
        cp16(s + G_BH + lrow * GST + lc8,        Bhg + boff0);
        cp16(s + G_BH + (lrow + 64) * GST + lc8, Bhg + boff1);
        cp16(s + G_BL + lrow * GST + lc8,        Blg + boff0);
        cp16(s + G_BL + (lrow + 64) * GST + lc8, Blg + boff1);
    };

    issue(0, 0);
    cp_commit();

    for (int t = 0; t < NT; ++t) {
        if (t + 1 < NT) { issue(t + 1, (t + 1) & 1); cp_commit(); cp_wait<1>(); }
        else            { cp_wait<0>(); }
        __syncthreads();

        const __nv_bfloat16* s = sm + (t & 1) * G_STAGE;
#pragma unroll
        for (int kk = 0; kk < 2; kk++) {
            uint32_t ah[2][4], al[2][4];
#pragma unroll
            for (int m = 0; m < 2; m++) {
                const int base = (m0 + m * 16 + g) * GST + kk * 16 + 2 * q;
                ah[m][0] = lds32(s + G_AH + base);
                ah[m][1] = lds32(s + G_AH + base + 8 * GST);
                ah[m][2] = lds32(s + G_AH + base + 8);
                ah[m][3] = lds32(s + G_AH + base + 8 * GST + 8);
                al[m][0] = lds32(s + G_AL + base);
                al[m][1] = lds32(s + G_AL + base + 8 * GST);
                al[m][2] = lds32(s + G_AL + base + 8);
                al[m][3] = lds32(s + G_AL + base + 8 * GST + 8);
            }
#pragma unroll
            for (int n = 0; n < 8; n++) {
                const int bb = (n0 + n * 8 + g) * GST + kk * 16 + 2 * q;
                uint32_t bh[2], bl[2];
                bh[0] = lds32(s + G_BH + bb);
                bh[1] = lds32(s + G_BH + bb + 8);
                bl[0] = lds32(s + G_BL + bb);
                bl[1] = lds32(s + G_BL + bb + 8);
#pragma unroll
                for (int m = 0; m < 2; m++) {
                    mma_bf16(c[m][n], ah[m], bh);
                    mma_bf16(c[m][n], al[m], bh);
                    mma_bf16(c[m][n], ah[m], bl);
                }
            }
        }
        __syncthreads();
    }

    // epilogue
#pragma unroll
    for (int m = 0; m < 2; m++) {
#pragma unroll
        for (int n = 0; n < 8; n++) {
            const int row = bRow + m0 + m * 16 + g;
            const int col = bCol + n0 + n * 8 + 2 * q;
#pragma unroll
            for (int half = 0; half < 2; half++) {
                const int r = row + half * 8;
                float v0 = c[m][n][half * 2 + 0];
                float v1 = c[m][n][half * 2 + 1];
                if (HAS_BIAS) { v0 += bias[col]; v1 += bias[col + 1]; }
                if (SPLIT_OUT) {
                    __nv_bfloat16 h0 = __float2bfloat16(v0);
                    __nv_bfloat16 h1 = __float2bfloat16(v1);
                    __nv_bfloat16 l0 = __float2bfloat16(v0 - __bfloat162float(h0));
                    __nv_bfloat16 l1 = __float2bfloat16(v1 - __bfloat162float(h1));
                    __nv_bfloat162 hp; hp.x = h0; hp.y = h1;
                    __nv_bfloat162 lp; lp.x = l0; lp.y = l1;
                    *reinterpret_cast<__nv_bfloat162*>(&Chg[(size_t)r * N + col]) = hp;
                    *reinterpret_cast<__nv_bfloat162*>(&Clg[(size_t)r * N + col]) = lp;
                } else {
                    float2 w; w.x = v0; w.y = v1;
                    *reinterpret_cast<float2*>(&Cf[(size_t)r * N + col]) = w;
                }
            }
        }
    }
}

// ---------------- split-bf16 causal flash attention --------------------------
// 256 thr (8 warps), 128-query x 64-key tiles. warp w: rows 16w..16w+15.
#define FST 72
#define FQ  (128 * FST)              // 9216 elems
#define FK  (64 * FST)               // 4608 elems
#define F_QH 0
#define F_QL FQ
#define F_KH (2 * FQ)
#define F_KL (2 * FQ + FK)
#define F_VH (2 * FQ + 2 * FK)
#define F_VL (2 * FQ + 3 * FK)
#define F_PH (2 * FQ + 4 * FK)
#define F_PL (3 * FQ + 4 * FK)
#define FLASH_SMEM ((4 * FQ + 4 * FK) * 2)   // 110592 bytes

__global__ __launch_bounds__(256, 2) void flash_sp(
    const __nv_bfloat16* __restrict__ qkvh,
    const __nv_bfloat16* __restrict__ qkvl,
    __nv_bfloat16* __restrict__ Oh, __nv_bfloat16* __restrict__ Ol)
{
    extern __shared__ __nv_bfloat16 fsm[];
    __nv_bfloat16* Qh = fsm + F_QH;  __nv_bfloat16* Ql = fsm + F_QL;
    __nv_bfloat16* Kh = fsm + F_KH;  __nv_bfloat16* Kl = fsm + F_KL;
    __nv_bfloat16* Vh = fsm + F_VH;  __nv_bfloat16* Vl = fsm + F_VL;
    __nv_bfloat16* Ph = fsm + F_PH;  __nv_bfloat16* Pl = fsm + F_PL;

    const int tid  = threadIdx.x;
    const int lane = tid & 31;
    const int wid  = tid >> 5;
    const int g    = lane >> 2;
    const int q    = lane & 3;
    const int qt   = blockIdx.x;         // 128-query tile (0..15)
    const int b    = blockIdx.y >> 4;
    const int h    = blockIdx.y & 15;
    const int q0   = qt * 128;
    const int rl0  = wid * 16 + g;       // 0..127
    const int rl1  = rl0 + 8;

    // load Q (scaled by 1/8, exact power of two)
    __nv_bfloat162 sc2; sc2.x = __float2bfloat16(0.125f); sc2.y = sc2.x;
#pragma unroll
    for (int l = 0; l < 4; l++) {
        const int idx = tid + l * 256;   // 0..1023
        const int r = idx >> 3;          // 0..127
        const int c8 = (idx & 7) * 8;
        const size_t off = (size_t)(b * TT + q0 + r) * QKV_COLS + h * HDIM + c8;
        uint4 vh4 = *reinterpret_cast<const uint4*>(qkvh + off);
        uint4 vl4 = *reinterpret_cast<const uint4*>(qkvl + off);
        __nv_bfloat162* ph = reinterpret_cast<__nv_bfloat162*>(&vh4);
        __nv_bfloat162* pl = reinterpret_cast<__nv_bfloat162*>(&vl4);
#pragma unroll
        for (int i = 0; i < 4; i++) { ph[i] = __hmul2(ph[i], sc2); pl[i] = __hmul2(pl[i], sc2); }
        *reinterpret_cast<uint4*>(&Qh[r * FST + c8]) = vh4;
        *reinterpret_cast<uint4*>(&Ql[r * FST + c8]) = vl4;
    }

    float m0r = -1e30f, m1r = -1e30f, l0r = 0.f, l1r = 0.f;
    float o[8][4];
#pragma unroll
    for (int j = 0; j < 8; j++)
#pragma unroll
        for (int r = 0; r < 4; r++) o[j][r] = 0.f;

    const int ktmax = 2 * qt + 1;
    for (int kt = 0; kt <= ktmax; kt++) {
        __syncthreads();
#pragma unroll
        for (int l = 0; l < 2; l++) {
            const int idx = tid + l * 256;   // 0..511
            const int r = idx >> 3;          // 0..63
            const int c8 = (idx & 7) * 8;
            const size_t base = (size_t)(b * TT + kt * 64 + r) * QKV_COLS + h * HDIM + c8;
            uint4 kh4 = *reinterpret_cast<const uint4*>(qkvh + base + DD);
            uint4 kl4 = *reinterpret_cast<const uint4*>(qkvl + base + DD);
            *reinterpret_cast<uint4*>(&Kh[r * FST + c8]) = kh4;
            *reinterpret_cast<uint4*>(&Kl[r * FST + c8]) = kl4;
            uint4 vh4 = *reinterpret_cast<const uint4*>(qkvh + base + 2 * DD);
            uint4 vl4 = *reinterpret_cast<const uint4*>(qkvl + base + 2 * DD);
            __nv_bfloat16 eh[8], el[8];
            *reinterpret_cast<uint4*>(eh) = vh4;
            *reinterpret_cast<uint4*>(el) = vl4;
#pragma unroll
            for (int i = 0; i < 8; i++) {
                Vh[(c8 + i) * FST + r] = eh[i];
                Vl[(c8 + i) * FST + r] = el[i];
            }
        }
        __syncthreads();

        // S = Q K^T (hh + lh + hl)
        float s[8][4];
#pragma unroll
        for (int j = 0; j < 8; j++)
#pragma unroll
            for (int r = 0; r < 4; r++) s[j][r] = 0.f;

#pragma unroll
        for (int kk = 0; kk < 4; kk++) {
            uint32_t qh[4], ql[4];
            const int base = rl0 * FST + kk * 16 + 2 * q;
            qh[0] = lds32(Qh + base);      qh[1] = lds32(Qh + base + 8 * FST);
            qh[2] = lds32(Qh + base + 8);  qh[3] = lds32(Qh + base + 8 * FST + 8);
            ql[0] = lds32(Ql + base);      ql[1] = lds32(Ql + base + 8 * FST);
            ql[2] = lds32(Ql + base + 8);  ql[3] = lds32(Ql + base + 8 * FST + 8);
#pragma unroll
            for (int j = 0; j < 8; j++) {
                const int bb = (j * 8 + g) * FST + kk * 16 + 2 * q;
                uint32_t kh2[2], kl2[2];
                kh2[0] = lds32(Kh + bb); kh2[1] = lds32(Kh + bb + 8);
                kl2[0] = lds32(Kl + bb); kl2[1] = lds32(Kl + bb + 8);
                mma_bf16(s[j], qh, kh2);
                mma_bf16(s[j], ql, kh2);
                mma_bf16(s[j], qh, kl2);
            }
        }

        if (kt >= 2 * qt) {   // diagonal region: elementwise causal mask
            const int coff = kt * 64 - q0;
#pragma unroll
            for (int j = 0; j < 8; j++) {
                const int c = coff + j * 8 + 2 * q;
                if (c     > rl0) s[j][0] = -1e30f;
                if (c + 1 > rl0) s[j][1] = -1e30f;
                if (c     > rl1) s[j][2] = -1e30f;
                if (c + 1 > rl1) s[j][3] = -1e30f;
            }
        }

        // online softmax
        {
            float tm = -1e30f;
#pragma unroll
            for (int j = 0; j < 8; j++) tm = fmaxf(tm, fmaxf(s[j][0], s[j][1]));
            tm = fmaxf(tm, __shfl_xor_sync(0xffffffffu, tm, 1));
            tm = fmaxf(tm, __shfl_xor_sync(0xffffffffu, tm, 2));
            const float mn = fmaxf(m0r, tm);
            const float corr = __expf(m0r - mn);
            m0r = mn;
            float rs = 0.f;
#pragma unroll
            for (int j = 0; j < 8; j++) {
                s[j][0] = __expf(s[j][0] - mn); rs += s[j][0];
                s[j][1] = __expf(s[j][1] - mn); rs += s[j][1];
            }
            rs += __shfl_xor_sync(0xffffffffu, rs, 1);
            rs += __shfl_xor_sync(0xffffffffu, rs, 2);
            l0r = l0r * corr + rs;
#pragma unroll
            for (int j = 0; j < 8; j++) { o[j][0] *= corr; o[j][1] *= corr; }
        }
        {
            float tm = -1e30f;
#pragma unroll
            for (int j = 0; j < 8; j++) tm = fmaxf(tm, fmaxf(s[j][2], s[j][3]));
            tm = fmaxf(tm, __shfl_xor_sync(0xffffffffu, tm, 1));
            tm = fmaxf(tm, __shfl_xor_sync(0xffffffffu, tm, 2));
            const float mn = fmaxf(m1r, tm);
            const float corr = __expf(m1r - mn);
            m1r = mn;
            float rs = 0.f;
#pragma unroll
            for (int j = 0; j < 8; j++) {
                s[j][2] = __expf(s[j][2] - mn); rs += s[j][2];
                s[j][3] = __expf(s[j][3] - mn); rs += s[j][3];
            }
            rs += __shfl_xor_sync(0xffffffffu, rs, 1);
            rs += __shfl_xor_sync(0xffffffffu, rs, 2);
            l1r = l1r * corr + rs;
#pragma unroll
            for (int j = 0; j < 8; j++) { o[j][2] *= corr; o[j][3] *= corr; }
        }

        // stage split P
#pragma unroll
        for (int j = 0; j < 8; j++) {
            const int col = j * 8 + 2 * q;
#pragma unroll
            for (int half = 0; half < 2; half++) {
                const int r = (half == 0) ? rl0 : rl1;
                const float v0 = s[j][half * 2 + 0];
                const float v1 = s[j][half * 2 + 1];
                __nv_bfloat16 h0 = __float2bfloat16(v0);
                __nv_bfloat16 h1 = __float2bfloat16(v1);
                __nv_bfloat16 l0v = __float2bfloat16(v0 - __bfloat162float(h0));
                __nv_bfloat16 l1v = __float2bfloat16(v1 - __bfloat162float(h1));
                __nv_bfloat162 hp; hp.x = h0; hp.y = h1;
                __nv_bfloat162 lp; lp.x = l0v; lp.y = l1v;
                *reinterpret_cast<__nv_bfloat162*>(&Ph[r * FST + col]) = hp;
                *reinterpret_cast<__nv_bfloat162*>(&Pl[r * FST + col]) = lp;
            }
        }
        __syncthreads();

        // O += P V
#pragma unroll
        for (int kk = 0; kk < 4; kk++) {
            uint32_t ph[4], pl[4];
            const int base = rl0 * FST + kk * 16 + 2 * q;
            ph[0] = lds32(Ph + base);      ph[1] = lds32(Ph + base + 8 * FST);
            ph[2] = lds32(Ph + base + 8);  ph[3] = lds32(Ph + base + 8 * FST + 8);
            pl[0] = lds32(Pl + base);      pl[1] = lds32(Pl + base + 8 * FST);
            pl[2] = lds32(Pl + base + 8);  pl[3] = lds32(Pl + base + 8 * FST + 8);
#pragma unroll
            for (int j = 0; j < 8; j++) {
                const int bb = (j * 8 + g) * FST + kk * 16 + 2 * q;
                uint32_t vh2[2], vl2[2];
                vh2[0] = lds32(Vh + bb); vh2[1] = lds32(Vh + bb + 8);
                vl2[0] = lds32(Vl + bb); vl2[1] = lds32(Vl + bb + 8);
                mma_bf16(o[j], ph, vh2);
                mma_bf16(o[j], pl, vh2);
                mma_bf16(o[j], ph, vl2);
            }
        }
    }

    // epilogue: normalize, split, store
    const float inv0 = 1.0f / l0r;
    const float inv1 = 1.0f / l1r;
#pragma unroll
    for (int j = 0; j < 8; j++) {
        const int col = h * HDIM + j * 8 + 2 * q;
#pragma unroll
        for (int half = 0; half < 2; half++) {
            const int r = (half == 0) ? rl0 : rl1;
            const float inv = (half == 0) ? inv0 : inv1;
            const float v0 = o[j][half * 2 + 0] * inv;
            const float v1 = o[j][half * 2 + 1] * inv;
            __nv_bfloat16 h0 = __float2bfloat16(v0);
            __nv_bfloat16 h1 = __float2bfloat16(v1);
            __nv_bfloat16 l0v = __float2bfloat16(v0 - __bfloat162float(h0));
            __nv_bfloat16 l1v = __float2bfloat16(v1 - __bfloat162float(h1));
            __nv_bfloat162 hp; hp.x = h0; hp.y = h1;
            __nv_bfloat162 lp; lp.x = l0v; lp.y = l1v;
            const size_t off = (size_t)(b * TT + q0 + r) * DD + col;
            *reinterpret_cast<__nv_bfloat162*>(&Oh[off]) = hp;
            *reinterpret_cast<__nv_bfloat162*>(&Ol[off]) = lp;
        }
    }
}

// ---------------------------------------------------------------------------
extern "C" void kernel_launch(void* const* d_in, const int* in_sizes, int n_in,
                              void* d_out, int out_size)
{
    const float* x     = (const float*)d_in[0];
    const float* Wqkv  = (const float*)d_in[1];
    const float* Wproj = (const float*)d_in[2];
    const float* bproj = (const float*)d_in[3];
    float* out = (float*)d_out;

    __nv_bfloat16 *xh, *xl, *wqh, *wql, *wph, *wpl, *qkvh, *qkvl, *ah, *al;
    cudaGetSymbolAddress((void**)&xh,   g_xh);
    cudaGetSymbolAddress((void**)&xl,   g_xl);
    cudaGetSymbolAddress((void**)&wqh,  g_wqh);
    cudaGetSymbolAddress((void**)&wql,  g_wql);
    cudaGetSymbolAddress((void**)&wph,  g_wph);
    cudaGetSymbolAddress((void**)&wpl,  g_wpl);
    cudaGetSymbolAddress((void**)&qkvh, g_qkvh);
    cudaGetSymbolAddress((void**)&qkvl, g_qkvl);
    cudaGetSymbolAddress((void**)&ah,   g_ah);
    cudaGetSymbolAddress((void**)&al,   g_al);

    cudaFuncSetAttribute(gemm_sp<true, false>,
                         cudaFuncAttributeMaxDynamicSharedMemorySize, GEMM_SMEM);
    cudaFuncSetAttribute(gemm_sp<false, true>,
                         cudaFuncAttributeMaxDynamicSharedMemorySize, GEMM_SMEM);
    cudaFuncSetAttribute(flash_sp,
                         cudaFuncAttributeMaxDynamicSharedMemorySize, FLASH_SMEM);

    // splits
    split_kernel<<<(MROWS * DD / 4 + 255) / 256, 256>>>(x, xh, xl, MROWS * DD / 4);
    split_kernel<<<(QKV_COLS * DD / 4 + 255) / 256, 256>>>(Wqkv, wqh, wql, QKV_COLS * DD / 4);
    split_kernel<<<(DD * DD / 4 + 255) / 256, 256>>>(Wproj, wph, wpl, DD * DD / 4);

    // 1) QKV projection (split output for attention)
    {
        dim3 grid(QKV_COLS / 128, MROWS / 128);
        gemm_sp<true, false><<<grid, 256, GEMM_SMEM>>>(
            xh, xl, wqh, wql, nullptr, nullptr, qkvh, qkvl, MROWS, QKV_COLS, DD);
    }
    // 2) causal flash attention (128q x 64k tiles)
    {
        dim3 grid(TT / 128, BB * HH);
        flash_sp<<<grid, 256, FLASH_SMEM>>>(qkvh, qkvl, ah, al);
    }
    // 3) output projection (fp32 out, bias)
    {
        dim3 grid(DD / 128, MROWS / 128);
        gemm_sp<false, true><<<grid, 256, GEMM_SMEM>>>(
            ah, al, wph, wpl, bproj, out, nullptr, nullptr, MROWS, DD, DD);
    }
}